// round 6
// baseline (speedup 1.0000x reference)
#include <cuda_runtime.h>
#include <cstdint>

// ---------------- problem constants ----------------
#define M_DIM 8192
#define K_DIM 4096
#define N_DIM 11008
#define NZ_DIM 1376
#define GS 128

// ---------------- GEMM tile config ----------------
#define BM 128
#define BN 256
#define BK 32
#define NSTAGES (K_DIM / BK)  // 128
#define SPIPE 4
#define GRPM 8

#define A_STAGE_BYTES (BM * 128)
#define B_STAGE_BYTES (BN * 128)
#define STAGE_BYTES (A_STAGE_BYTES + B_STAGE_BYTES)
#define SMEM_TOTAL (SPIPE * STAGE_BYTES)   // 196608

#define MTILES (M_DIM / BM)   // 64
#define NTILES (N_DIM / BN)   // 43

// K-permutation within each 32-k block: p = (k&3)*8 + (k>>2)
// => a thread's fragment values (cols tg+4j, j=0..7) are contiguous.

// ---------------- scratch ----------------
__device__ float g_wt[(size_t)N_DIM * K_DIM];   // dequant W^T, tf32, k-permuted per 32-block: [N, K]
__device__ float g_ax[(size_t)M_DIM * K_DIM];   // x tf32, k-permuted per 32-block: [M, K]

// ---------------- helpers ----------------
__device__ __forceinline__ uint32_t f2tf32(float f) {
    uint32_t r; asm("cvt.rna.tf32.f32 %0, %1;" : "=r"(r) : "f"(f)); return r;
}
__device__ __forceinline__ void cp16(uint32_t saddr, const float* g) {
    asm volatile("cp.async.cg.shared.global [%0], [%1], 16;" :: "r"(saddr), "l"(g));
}
__device__ __forceinline__ void cp_commit() { asm volatile("cp.async.commit_group;" ::: "memory"); }
__device__ __forceinline__ void cp_wait3()  { asm volatile("cp.async.wait_group 3;" ::: "memory"); }
__device__ __forceinline__ uint32_t smem_u32(const void* p) {
    uint32_t a;
    asm("{ .reg .u64 t; cvta.to.shared.u64 t, %1; cvt.u32.u64 %0, t; }" : "=r"(a) : "l"(p));
    return a;
}

// ---------------- prep: round x to tf32, k-permuted ----------------
// One thread per 32-k block of one row.
extern "C" __global__ void round_a_kernel(const float* __restrict__ x) {
    int idx = blockIdx.x * 256 + threadIdx.x;      // 0 .. 8192*128-1
    int kb  = idx & 127;                           // 32-k block
    int m   = idx >> 7;
    const float4* src = (const float4*)(x + (size_t)m * K_DIM + kb * 32);
    float dst[32];
    #pragma unroll
    for (int i = 0; i < 8; i++) {
        float4 v = src[i];
        int k = i * 4;
        dst[((k + 0) & 3) * 8 + ((k + 0) >> 2)] = __uint_as_float(f2tf32(v.x));
        dst[((k + 1) & 3) * 8 + ((k + 1) >> 2)] = __uint_as_float(f2tf32(v.y));
        dst[((k + 2) & 3) * 8 + ((k + 2) >> 2)] = __uint_as_float(f2tf32(v.z));
        dst[((k + 3) & 3) * 8 + ((k + 3) >> 2)] = __uint_as_float(f2tf32(v.w));
    }
    float4* d = (float4*)(g_ax + (size_t)m * K_DIM + kb * 32);
    #pragma unroll
    for (int i = 0; i < 8; i++)
        d[i] = make_float4(dst[4 * i], dst[4 * i + 1], dst[4 * i + 2], dst[4 * i + 3]);
}

// ---------------- prep: dequant + transpose W -> tf32 [N, K], k-permuted ----------------
// One thread per (n, 32-k block): reads 4 packed words, writes 128B contiguous.
extern "C" __global__ void dequant_wt_kernel(const uint32_t* __restrict__ qweight,
                                             const float* __restrict__ scales,
                                             const uint32_t* __restrict__ qzeros) {
    int n  = blockIdx.x * 256 + threadIdx.x;   // 0..11007
    int kb = blockIdx.y;                       // 0..127
    int g  = kb >> 2;                          // group (32k per block, 128 per group)
    float    s  = scales[(size_t)g * N_DIM + n];
    uint32_t zq = qzeros[(size_t)g * NZ_DIM + (n >> 3)];
    float    sz = s * (float)((zq >> ((n & 7) * 4)) & 0xF);
    float dst[32];
    #pragma unroll
    for (int i = 0; i < 4; i++) {
        uint32_t q = qweight[(size_t)(kb * 4 + i) * N_DIM + n];
        #pragma unroll
        for (int j = 0; j < 8; j++) {
            int k = i * 8 + j;
            dst[(k & 3) * 8 + (k >> 2)] =
                __uint_as_float(f2tf32(fmaf(s, (float)((q >> (4 * j)) & 0xF), -sz)));
        }
    }
    float4* d = (float4*)(g_wt + (size_t)n * K_DIM + kb * 32);
    #pragma unroll
    for (int i = 0; i < 8; i++)
        d[i] = make_float4(dst[4 * i], dst[4 * i + 1], dst[4 * i + 2], dst[4 * i + 3]);
}

// ---------------- main GEMM ----------------
extern "C" __global__ void __launch_bounds__(256, 1)
qgemm_tf32(float* __restrict__ out) {
    extern __shared__ char smem[];
    uint32_t sb = smem_u32(smem);

    const int t = threadIdx.x;
    const int warp = t >> 5, lane = t & 31;
    const int g8 = lane >> 2, tg = lane & 3;
    const int warp_m = warp >> 2;    // 0..1
    const int warp_n = warp & 3;     // 0..3

    const int bid   = blockIdx.x;
    const int group = bid / (GRPM * NTILES);
    const int rem   = bid % (GRPM * NTILES);
    const int m0    = (group * GRPM + (rem % GRPM)) * BM;
    const int n0    = (rem / GRPM) * BN;

    float c[4][8][4];
    #pragma unroll
    for (int i = 0; i < 4; i++)
        #pragma unroll
        for (int j = 0; j < 8; j++)
            #pragma unroll
            for (int k = 0; k < 4; k++) c[i][j][k] = 0.f;

    // ---- cp.async addresses ----
    // smem layout: row*128 + (g>>1)*32 + (((g&1)^(row&1))<<4)   [g = 16B granule 0..7]
    const float* a_g[4]; uint32_t a_s[4];
    #pragma unroll
    for (int i = 0; i < 4; i++) {
        int idx = t + i * 256;
        int r = idx >> 3, g = idx & 7;
        a_g[i] = g_ax + (size_t)(m0 + r) * K_DIM + g * 4;
        a_s[i] = sb + r * 128 + (g >> 1) * 32 + (((g & 1) ^ (r & 1)) << 4);
    }
    const float* b_g[8]; uint32_t b_s[8];
    #pragma unroll
    for (int i = 0; i < 8; i++) {
        int idx = t + i * 256;
        int r = idx >> 3, g = idx & 7;
        b_g[i] = g_wt + (size_t)(n0 + r) * K_DIM + g * 4;
        b_s[i] = sb + A_STAGE_BYTES + r * 128 + (g >> 1) * 32 + (((g & 1) ^ (r & 1)) << 4);
    }

    auto fill = [&](int s) {
        int off = (s & (SPIPE - 1)) * STAGE_BYTES;
        #pragma unroll
        for (int i = 0; i < 4; i++) cp16(a_s[i] + off, a_g[i] + s * BK);
        #pragma unroll
        for (int i = 0; i < 8; i++) cp16(b_s[i] + off, b_g[i] + s * BK);
        cp_commit();
    };

    fill(0); fill(1); fill(2);

    // fragment LDS.128 sub-offset: tg*2 + (h ^ parity), parity = g8&1 (all frag rows share it)
    const int par = g8 & 1;

    for (int s = 0; s < NSTAGES; s++) {
        if (s + 3 < NSTAGES) fill(s + 3); else cp_commit();
        cp_wait3();
        __syncthreads();

        const uint4* A4 = (const uint4*)(smem + (s & (SPIPE - 1)) * STAGE_BYTES);
        const uint4* B4 = (const uint4*)(smem + (s & (SPIPE - 1)) * STAGE_BYTES + A_STAGE_BYTES);

        #pragma unroll
        for (int h = 0; h < 2; h++) {           // h=0: kk{0,8}, h=1: kk{16,24}
            const int sub = tg * 2 + (h ^ par);
            uint4 afr[4][2];
            #pragma unroll
            for (int mi = 0; mi < 4; mi++) {
                int r0 = warp_m * 64 + mi * 16 + g8;
                afr[mi][0] = A4[r0 * 8 + sub];
                afr[mi][1] = A4[(r0 + 8) * 8 + sub];
            }
            uint4 bfr[8];
            #pragma unroll
            for (int ni = 0; ni < 8; ni++) {
                int r = warp_n * 64 + ni * 8 + g8;
                bfr[ni] = B4[r * 8 + sub];
            }
            // q=0: (x,y) components; q=1: (z,w)
            #pragma unroll
            for (int mi = 0; mi < 4; mi++)
                #pragma unroll
                for (int ni = 0; ni < 8; ni++) {
                    asm volatile(
                        "mma.sync.aligned.m16n8k8.row.col.f32.tf32.tf32.f32 "
                        "{%0,%1,%2,%3}, {%4,%5,%6,%7}, {%8,%9}, {%0,%1,%2,%3};"
                        : "+f"(c[mi][ni][0]), "+f"(c[mi][ni][1]),
                          "+f"(c[mi][ni][2]), "+f"(c[mi][ni][3])
                        : "r"(afr[mi][0].x), "r"(afr[mi][1].x),
                          "r"(afr[mi][0].y), "r"(afr[mi][1].y),
                          "r"(bfr[ni].x), "r"(bfr[ni].y));
                }
            #pragma unroll
            for (int mi = 0; mi < 4; mi++)
                #pragma unroll
                for (int ni = 0; ni < 8; ni++) {
                    asm volatile(
                        "mma.sync.aligned.m16n8k8.row.col.f32.tf32.tf32.f32 "
                        "{%0,%1,%2,%3}, {%4,%5,%6,%7}, {%8,%9}, {%0,%1,%2,%3};"
                        : "+f"(c[mi][ni][0]), "+f"(c[mi][ni][1]),
                          "+f"(c[mi][ni][2]), "+f"(c[mi][ni][3])
                        : "r"(afr[mi][0].z), "r"(afr[mi][1].z),
                          "r"(afr[mi][0].w), "r"(afr[mi][1].w),
                          "r"(bfr[ni].z), "r"(bfr[ni].w));
                }
        }
    }

    // ---- epilogue ----
    #pragma unroll
    for (int mi = 0; mi < 4; mi++) {
        int row = m0 + warp_m * 64 + mi * 16 + g8;
        float* o0 = out + (size_t)row * N_DIM;
        float* o1 = out + (size_t)(row + 8) * N_DIM;
        #pragma unroll
        for (int ni = 0; ni < 8; ni++) {
            int col = n0 + warp_n * 64 + ni * 8 + 2 * tg;
            *(float2*)(o0 + col) = make_float2(c[mi][ni][0], c[mi][ni][1]);
            *(float2*)(o1 + col) = make_float2(c[mi][ni][2], c[mi][ni][3]);
        }
    }
}

// ---------------- launch ----------------
extern "C" void kernel_launch(void* const* d_in, const int* in_sizes, int n_in,
                              void* d_out, int out_size) {
    const float*    x       = (const float*)d_in[0];
    const uint32_t* qweight = (const uint32_t*)d_in[1];
    const float*    scales  = (const float*)d_in[2];
    const uint32_t* qzeros  = (const uint32_t*)d_in[3];
    float*          out     = (float*)d_out;

    cudaFuncSetAttribute(qgemm_tf32,
                         cudaFuncAttributeMaxDynamicSharedMemorySize, SMEM_TOTAL);

    round_a_kernel<<<M_DIM * (K_DIM / 32) / 256, 256>>>(x);
    dim3 dq_grid(N_DIM / 256, K_DIM / 32);   // (43, 128)
    dequant_wt_kernel<<<dq_grid, 256>>>(qweight, scales, qzeros);
    qgemm_tf32<<<MTILES * NTILES, 256, SMEM_TOTAL>>>(out);
}

// round 7
// speedup vs baseline: 1.1273x; 1.1273x over previous
#include <cuda_runtime.h>
#include <cstdint>

// ---------------- problem constants ----------------
#define M_DIM 8192
#define K_DIM 4096
#define N_DIM 11008
#define NZ_DIM 1376
#define GS 128

// ---------------- GEMM tile config ----------------
#define BM 128
#define BN 256
#define BK 32
#define NSTAGES (K_DIM / BK)  // 128
#define SPIPE 4
#define GRPM 8

#define A_STAGE_BYTES (BM * 128)
#define B_STAGE_BYTES (BN * 128)
#define STAGE_BYTES (A_STAGE_BYTES + B_STAGE_BYTES)
#define SMEM_TOTAL (SPIPE * STAGE_BYTES)   // 196608

#define MTILES (M_DIM / BM)   // 64
#define NTILES (N_DIM / BN)   // 43

// ---------------- scratch ----------------
__device__ float g_wt[(size_t)N_DIM * K_DIM];   // dequant W^T tf32: [N, K]
__device__ float g_ax[(size_t)M_DIM * K_DIM];   // x tf32: [M, K]

// ---------------- helpers ----------------
__device__ __forceinline__ uint32_t f2tf32(float f) {
    uint32_t r; asm("cvt.rna.tf32.f32 %0, %1;" : "=r"(r) : "f"(f)); return r;
}
__device__ __forceinline__ void cp16(uint32_t saddr, const float* g) {
    asm volatile("cp.async.cg.shared.global [%0], [%1], 16;" :: "r"(saddr), "l"(g));
}
__device__ __forceinline__ void cp_commit() { asm volatile("cp.async.commit_group;" ::: "memory"); }
__device__ __forceinline__ void cp_wait3()  { asm volatile("cp.async.wait_group 3;" ::: "memory"); }
__device__ __forceinline__ uint32_t smem_u32(const void* p) {
    uint32_t a;
    asm("{ .reg .u64 t; cvta.to.shared.u64 t, %1; cvt.u32.u64 %0, t; }" : "=r"(a) : "l"(p));
    return a;
}

// ---------------- prep: round x to tf32 (coalesced, one float4/thread) ----------------
extern "C" __global__ void round_a_kernel(const float4* __restrict__ x) {
    size_t i = (size_t)blockIdx.x * blockDim.x + threadIdx.x;
    float4 v = x[i];
    float4 r;
    r.x = __uint_as_float(f2tf32(v.x));
    r.y = __uint_as_float(f2tf32(v.y));
    r.z = __uint_as_float(f2tf32(v.z));
    r.w = __uint_as_float(f2tf32(v.w));
    ((float4*)g_ax)[i] = r;
}

// ---------------- prep: dequant + transpose W -> tf32 [N, K] (coalesced) ----------------
extern "C" __global__ void dequant_wt_kernel(const uint32_t* __restrict__ qweight,
                                             const float* __restrict__ scales,
                                             const uint32_t* __restrict__ qzeros) {
    int n  = blockIdx.x * blockDim.x + threadIdx.x;   // 0..11007
    int kp = blockIdx.y;                              // 0..511 packed k-row (8 k each)
    int g  = kp >> 4;
    uint32_t q  = qweight[(size_t)kp * N_DIM + n];
    float    s  = scales[(size_t)g * N_DIM + n];
    uint32_t zq = qzeros[(size_t)g * NZ_DIM + (n >> 3)];
    float    sz = s * (float)((zq >> ((n & 7) * 4)) & 0xF);
    float w[8];
    #pragma unroll
    for (int j = 0; j < 8; j++)
        w[j] = __uint_as_float(f2tf32(fmaf(s, (float)((q >> (4 * j)) & 0xF), -sz)));
    float4* dst = (float4*)(g_wt + (size_t)n * K_DIM + kp * 8);
    dst[0] = make_float4(w[0], w[1], w[2], w[3]);
    dst[1] = make_float4(w[4], w[5], w[6], w[7]);
}

// ---------------- main GEMM: tf32 mma.sync, reg-pipelined fragments ----------------
extern "C" __global__ void __launch_bounds__(256, 1)
qgemm_tf32(float* __restrict__ out) {
    extern __shared__ char smem[];
    uint32_t sb = smem_u32(smem);

    const int t = threadIdx.x;
    const int warp = t >> 5, lane = t & 31;
    const int g8 = lane >> 2, tg = lane & 3;
    const int warp_m = warp >> 2;    // 0..1 -> 64 rows
    const int warp_n = warp & 3;     // 0..3 -> 64 cols

    const int bid   = blockIdx.x;
    const int group = bid / (GRPM * NTILES);
    const int rem   = bid % (GRPM * NTILES);
    const int m0    = (group * GRPM + (rem % GRPM)) * BM;
    const int n0    = (rem / GRPM) * BN;

    float c[4][8][4];
    #pragma unroll
    for (int i = 0; i < 4; i++)
        #pragma unroll
        for (int j = 0; j < 8; j++)
            #pragma unroll
            for (int k = 0; k < 4; k++) c[i][j][k] = 0.f;

    // ---- cp.async addresses (SW128 swizzle on 128B rows) ----
    const float* a_g[4]; uint32_t a_s[4];
    #pragma unroll
    for (int i = 0; i < 4; i++) {
        int idx = t + i * 256;
        int r = idx >> 3, g = idx & 7;
        a_g[i] = g_ax + (size_t)(m0 + r) * K_DIM + g * 4;
        a_s[i] = sb + r * 128 + ((g ^ (r & 7)) << 4);
    }
    const float* b_g[8]; uint32_t b_s[8];
    #pragma unroll
    for (int i = 0; i < 8; i++) {
        int idx = t + i * 256;
        int r = idx >> 3, g = idx & 7;
        b_g[i] = g_wt + (size_t)(n0 + r) * K_DIM + g * 4;
        b_s[i] = sb + A_STAGE_BYTES + r * 128 + ((g ^ (r & 7)) << 4);
    }

    auto fill = [&](int s) {
        int off = (s & (SPIPE - 1)) * STAGE_BYTES;
        #pragma unroll
        for (int i = 0; i < 4; i++) cp16(a_s[i] + off, a_g[i] + s * BK);
        #pragma unroll
        for (int i = 0; i < 8; i++) cp16(b_s[i] + off, b_g[i] + s * BK);
        cp_commit();
    };

    fill(0); fill(1); fill(2);

    const int axor = g8 << 2;   // swizzle xor (row&7 == g8 for all fragment rows)

    // double-buffered fragment registers
    uint32_t af[2][4][4];
    uint32_t bf[2][8][2];

    auto load_frag = [&](const uint32_t* A, const uint32_t* B, int kk, int buf) {
        #pragma unroll
        for (int mi = 0; mi < 4; mi++) {
            int r = warp_m * 64 + mi * 16 + g8;
            const uint32_t* ap = A + r * 32;
            af[buf][mi][0] = ap[(kk + tg) ^ axor];
            af[buf][mi][1] = ap[8 * 32 + ((kk + tg) ^ axor)];
            af[buf][mi][2] = ap[(kk + 4 + tg) ^ axor];
            af[buf][mi][3] = ap[8 * 32 + ((kk + 4 + tg) ^ axor)];
        }
        #pragma unroll
        for (int ni = 0; ni < 8; ni++) {
            int r = warp_n * 64 + ni * 8 + g8;
            const uint32_t* bp = B + r * 32;
            bf[buf][ni][0] = bp[(kk + tg) ^ axor];
            bf[buf][ni][1] = bp[(kk + 4 + tg) ^ axor];
        }
    };

    auto do_mmas = [&](int buf) {
        #pragma unroll
        for (int mi = 0; mi < 4; mi++)
            #pragma unroll
            for (int ni = 0; ni < 8; ni++) {
                asm volatile(
                    "mma.sync.aligned.m16n8k8.row.col.f32.tf32.tf32.f32 "
                    "{%0,%1,%2,%3}, {%4,%5,%6,%7}, {%8,%9}, {%0,%1,%2,%3};"
                    : "+f"(c[mi][ni][0]), "+f"(c[mi][ni][1]),
                      "+f"(c[mi][ni][2]), "+f"(c[mi][ni][3])
                    : "r"(af[buf][mi][0]), "r"(af[buf][mi][1]),
                      "r"(af[buf][mi][2]), "r"(af[buf][mi][3]),
                      "r"(bf[buf][ni][0]), "r"(bf[buf][ni][1]));
            }
    };

    for (int s = 0; s < NSTAGES; s++) {
        if (s + 3 < NSTAGES) fill(s + 3); else cp_commit();
        cp_wait3();
        __syncthreads();

        const uint32_t* A = (const uint32_t*)(smem + (s & (SPIPE - 1)) * STAGE_BYTES);
        const uint32_t* B = A + A_STAGE_BYTES / 4;

        load_frag(A, B, 0, 0);
        #pragma unroll
        for (int kb = 0; kb < 4; kb++) {
            if (kb < 3) load_frag(A, B, (kb + 1) * 8, (kb + 1) & 1);  // prefetch next block
            do_mmas(kb & 1);                                          // overlap with loads
        }
    }

    // ---- epilogue ----
    #pragma unroll
    for (int mi = 0; mi < 4; mi++) {
        int row = m0 + warp_m * 64 + mi * 16 + g8;
        float* o0 = out + (size_t)row * N_DIM;
        float* o1 = out + (size_t)(row + 8) * N_DIM;
        #pragma unroll
        for (int ni = 0; ni < 8; ni++) {
            int col = n0 + warp_n * 64 + ni * 8 + 2 * tg;
            *(float2*)(o0 + col) = make_float2(c[mi][ni][0], c[mi][ni][1]);
            *(float2*)(o1 + col) = make_float2(c[mi][ni][2], c[mi][ni][3]);
        }
    }
}

// ---------------- launch ----------------
extern "C" void kernel_launch(void* const* d_in, const int* in_sizes, int n_in,
                              void* d_out, int out_size) {
    const float*    x       = (const float*)d_in[0];
    const uint32_t* qweight = (const uint32_t*)d_in[1];
    const float*    scales  = (const float*)d_in[2];
    const uint32_t* qzeros  = (const uint32_t*)d_in[3];
    float*          out     = (float*)d_out;

    cudaFuncSetAttribute(qgemm_tf32,
                         cudaFuncAttributeMaxDynamicSharedMemorySize, SMEM_TOTAL);

    round_a_kernel<<<(unsigned)((size_t)M_DIM * K_DIM / 4 / 256), 256>>>((const float4*)x);
    dim3 dq_grid(N_DIM / 256, K_DIM / 8);   // (43, 512)
    dequant_wt_kernel<<<dq_grid, 256>>>(qweight, scales, qzeros);
    qgemm_tf32<<<MTILES * NTILES, 256, SMEM_TOTAL>>>(out);
}